// round 4
// baseline (speedup 1.0000x reference)
#include <cuda_runtime.h>
#include <math.h>

#define C_DIM 512
#define HW_DIM 4096
#define B_DIM 8
#define N_TOK (B_DIM * HW_DIM)       // 32768 tokens
#define ALPHA_V 0.044194173824159216f
#define EPS_V 1e-6f

// ---------------- scratch (device globals: allocation-free) ----------------
__device__ float g_h[(size_t)N_TOK * C_DIM];                 // h (token-major), later attn_out
__device__ float g_q[(size_t)N_TOK * C_DIM];                 // q, later o_proj
__device__ float g_k[(size_t)N_TOK * C_DIM];
__device__ float g_v[(size_t)N_TOK * C_DIM];
__device__ float g_s[(size_t)B_DIM * HW_DIM * HW_DIM];       // scores (512 MB)

// ---------------- reduction helpers ----------------
__inline__ __device__ float warpMax(float v) {
    #pragma unroll
    for (int o = 16; o > 0; o >>= 1) v = fmaxf(v, __shfl_xor_sync(0xffffffffu, v, o));
    return v;
}
__inline__ __device__ float warpSum(float v) {
    #pragma unroll
    for (int o = 16; o > 0; o >>= 1) v += __shfl_xor_sync(0xffffffffu, v, o);
    return v;
}

// ---------------- GroupNorm + transpose to token-major ----------------
// grid: B*G = 256 blocks of 256 threads; each block = one (batch, group) of 16 ch x 4096
__global__ void groupnorm_kernel(const float* __restrict__ x,
                                 const float* __restrict__ gamma,
                                 const float* __restrict__ beta,
                                 float* __restrict__ h) {
    const int b = blockIdx.x >> 5;
    const int g = blockIdx.x & 31;
    const float* xp = x + ((size_t)b * C_DIM + g * 16) * HW_DIM;
    const int tid = threadIdx.x;

    float s = 0.f, ss = 0.f;
    for (int i = tid; i < 16 * HW_DIM; i += 256) {
        float v = xp[i];
        s += v; ss += v * v;
    }
    __shared__ float r1[8], r2[8];
    float ws = warpSum(s), wss = warpSum(ss);
    if ((tid & 31) == 0) { r1[tid >> 5] = ws; r2[tid >> 5] = wss; }
    __syncthreads();
    __shared__ float s_mu, s_rs;
    if (tid == 0) {
        float S = 0.f, SS = 0.f;
        #pragma unroll
        for (int i = 0; i < 8; i++) { S += r1[i]; SS += r2[i]; }
        float mu = S * (1.f / 65536.f);
        float var = SS * (1.f / 65536.f) - mu * mu;
        s_mu = mu;
        s_rs = rsqrtf(var + EPS_V);
    }
    __syncthreads();
    const float mu = s_mu, rs = s_rs;

    for (int i = tid; i < 16 * HW_DIM; i += 256) {
        int cl = i >> 12;
        int hw = i & (HW_DIM - 1);
        int c = g * 16 + cl;
        float v = (xp[i] - mu) * rs * gamma[c] + beta[c];
        h[((size_t)b * HW_DIM + hw) * C_DIM + c] = v;
    }
}

// ---------------- generic fp32 tiled GEMM ----------------
// C = alpha * A @ op(B) + bias
//   A: [M x K] row-major
//   TRANS_B: B is [N x K] row-major (NT)   else: B is [K x N] row-major (NN)
// Tiles: 128x128x16, 256 threads, 8x8 micro-tile per thread.
#define BM 128
#define BN 128
#define BKT 16
#define BMP 140   // padded smem row (float4-aligned, conflict-mitigating)

template <bool TRANS_B, bool HAS_BIAS>
__global__ __launch_bounds__(256, 2)
void gemm_kernel(const float* __restrict__ A, const float* __restrict__ B,
                 const float* __restrict__ bias, float* __restrict__ Cmat,
                 int M, int N, int K,
                 long long strideA, long long strideB, long long strideC,
                 float alpha) {
    __shared__ float As[BKT][BMP];
    __shared__ float Bs[BKT][BMP];

    const float* Ab = A + (size_t)blockIdx.z * strideA;
    const float* Bb = B + (size_t)blockIdx.z * strideB;
    float* Cb = Cmat + (size_t)blockIdx.z * strideC;

    const int tid = threadIdx.x;
    const int tx = tid & 15;   // N direction
    const int ty = tid >> 4;   // M direction
    const int mBase = blockIdx.y * BM;
    const int nBase = blockIdx.x * BN;

    // NT-style loader indices (also used for A)
    const int lrow = tid >> 2;        // 0..63
    const int lk = (tid & 3) * 4;     // 0,4,8,12
    // NN B loader indices
    const int bn = (tid & 31) * 4;    // 0..124
    const int bk = tid >> 5;          // 0..7

    const float* Aptr = Ab + (size_t)(mBase + lrow) * K + lk;

    float acc[8][8];
    #pragma unroll
    for (int i = 0; i < 8; i++)
        #pragma unroll
        for (int j = 0; j < 8; j++) acc[i][j] = 0.f;

    for (int kt = 0; kt < K; kt += BKT) {
        // --- load A tile (rows lrow, lrow+64) ---
        float4 a0 = *(const float4*)(Aptr + kt);
        float4 a1 = *(const float4*)(Aptr + kt + (size_t)64 * K);
        As[lk + 0][lrow] = a0.x; As[lk + 1][lrow] = a0.y;
        As[lk + 2][lrow] = a0.z; As[lk + 3][lrow] = a0.w;
        As[lk + 0][lrow + 64] = a1.x; As[lk + 1][lrow + 64] = a1.y;
        As[lk + 2][lrow + 64] = a1.z; As[lk + 3][lrow + 64] = a1.w;

        // --- load B tile ---
        if (TRANS_B) {
            const float* Bptr = Bb + (size_t)(nBase + lrow) * K + kt + lk;
            float4 b0 = *(const float4*)(Bptr);
            float4 b1 = *(const float4*)(Bptr + (size_t)64 * K);
            Bs[lk + 0][lrow] = b0.x; Bs[lk + 1][lrow] = b0.y;
            Bs[lk + 2][lrow] = b0.z; Bs[lk + 3][lrow] = b0.w;
            Bs[lk + 0][lrow + 64] = b1.x; Bs[lk + 1][lrow + 64] = b1.y;
            Bs[lk + 2][lrow + 64] = b1.z; Bs[lk + 3][lrow + 64] = b1.w;
        } else {
            const float* Bptr = Bb + (size_t)(kt + bk) * N + nBase + bn;
            *(float4*)&Bs[bk][bn] = *(const float4*)Bptr;
            *(float4*)&Bs[bk + 8][bn] = *(const float4*)(Bptr + (size_t)8 * N);
        }
        __syncthreads();

        #pragma unroll
        for (int kk = 0; kk < BKT; kk++) {
            float a[8], b[8];
            *(float4*)&a[0] = *(const float4*)&As[kk][ty * 4];
            *(float4*)&a[4] = *(const float4*)&As[kk][64 + ty * 4];
            *(float4*)&b[0] = *(const float4*)&Bs[kk][tx * 4];
            *(float4*)&b[4] = *(const float4*)&Bs[kk][64 + tx * 4];
            #pragma unroll
            for (int i = 0; i < 8; i++)
                #pragma unroll
                for (int j = 0; j < 8; j++)
                    acc[i][j] += a[i] * b[j];
        }
        __syncthreads();
    }

    // --- epilogue ---
    float bl[8];
    if (HAS_BIAS) {
        #pragma unroll
        for (int j = 0; j < 4; j++) {
            bl[j] = bias[nBase + tx * 4 + j];
            bl[4 + j] = bias[nBase + 64 + tx * 4 + j];
        }
    } else {
        #pragma unroll
        for (int j = 0; j < 8; j++) bl[j] = 0.f;
    }

    #pragma unroll
    for (int i = 0; i < 8; i++) {
        int m = mBase + ((i < 4) ? (ty * 4 + i) : (64 + ty * 4 + i - 4));
        float4 lo, hi;
        lo.x = acc[i][0] * alpha + bl[0];
        lo.y = acc[i][1] * alpha + bl[1];
        lo.z = acc[i][2] * alpha + bl[2];
        lo.w = acc[i][3] * alpha + bl[3];
        hi.x = acc[i][4] * alpha + bl[4];
        hi.y = acc[i][5] * alpha + bl[5];
        hi.z = acc[i][6] * alpha + bl[6];
        hi.w = acc[i][7] * alpha + bl[7];
        *(float4*)&Cb[(size_t)m * N + nBase + tx * 4] = lo;
        *(float4*)&Cb[(size_t)m * N + nBase + 64 + tx * 4] = hi;
    }
}

// ---------------- row softmax over 4096 (one block per row) ----------------
__global__ void softmax_kernel(float* __restrict__ S) {
    float* p = S + (size_t)blockIdx.x * HW_DIM;
    const int tid = threadIdx.x;
    float v[16];
    float mx = -1e30f;
    #pragma unroll
    for (int i = 0; i < 16; i++) {
        v[i] = p[tid + i * 256];
        mx = fmaxf(mx, v[i]);
    }
    __shared__ float sm[8];
    float w = warpMax(mx);
    if ((tid & 31) == 0) sm[tid >> 5] = w;
    __syncthreads();
    if (tid < 32) {
        float t = (tid < 8) ? sm[tid] : -1e30f;
        t = warpMax(t);
        if (tid == 0) sm[0] = t;
    }
    __syncthreads();
    const float bm = sm[0];
    __syncthreads();

    float sum = 0.f;
    #pragma unroll
    for (int i = 0; i < 16; i++) {
        v[i] = __expf(v[i] - bm);
        sum += v[i];
    }
    float ws = warpSum(sum);
    if ((tid & 31) == 0) sm[tid >> 5] = ws;
    __syncthreads();
    if (tid < 32) {
        float t = (tid < 8) ? sm[tid] : 0.f;
        t = warpSum(t);
        if (tid == 0) sm[0] = t;
    }
    __syncthreads();
    const float inv = 1.0f / sm[0];
    #pragma unroll
    for (int i = 0; i < 16; i++) p[tid + i * 256] = v[i] * inv;
}

// ---------------- transpose back to [B,C,HW] + residual ----------------
// grid (HW/32, C/32, B), block (32, 8)
__global__ void add_res_transpose_kernel(const float* __restrict__ op,
                                         const float* __restrict__ x,
                                         float* __restrict__ out) {
    __shared__ float t[32][33];
    const int b = blockIdx.z;
    const int hw0 = blockIdx.x * 32;
    const int c0 = blockIdx.y * 32;
    for (int r = threadIdx.y; r < 32; r += 8)
        t[r][threadIdx.x] = op[((size_t)b * HW_DIM + hw0 + r) * C_DIM + c0 + threadIdx.x];
    __syncthreads();
    for (int r = threadIdx.y; r < 32; r += 8) {
        int c = c0 + r;
        size_t idx = ((size_t)b * C_DIM + c) * HW_DIM + hw0 + threadIdx.x;
        out[idx] = t[threadIdx.x][r] + x[idx];
    }
}

// ---------------- launch ----------------
extern "C" void kernel_launch(void* const* d_in, const int* in_sizes, int n_in,
                              void* d_out, int out_size) {
    const float* x     = (const float*)d_in[0];
    const float* gamma = (const float*)d_in[1];
    const float* beta  = (const float*)d_in[2];
    const float* wq = (const float*)d_in[3]; const float* bq = (const float*)d_in[4];
    const float* wk = (const float*)d_in[5]; const float* bk = (const float*)d_in[6];
    const float* wv = (const float*)d_in[7]; const float* bv = (const float*)d_in[8];
    const float* wo = (const float*)d_in[9]; const float* bo = (const float*)d_in[10];
    float* out = (float*)d_out;

    float *h, *q, *k, *v, *s;
    cudaGetSymbolAddress((void**)&h, g_h);
    cudaGetSymbolAddress((void**)&q, g_q);
    cudaGetSymbolAddress((void**)&k, g_k);
    cudaGetSymbolAddress((void**)&v, g_v);
    cudaGetSymbolAddress((void**)&s, g_s);

    // 1. GroupNorm (+ transpose to token-major h)
    groupnorm_kernel<<<B_DIM * 32, 256>>>(x, gamma, beta, h);

    // 2. Q/K/V projections: [32768 x 512] = h @ W^T + b   (NT)
    dim3 gproj(C_DIM / BN, N_TOK / BM, 1);
    gemm_kernel<true, true><<<gproj, 256>>>(h, wq, bq, q, N_TOK, C_DIM, C_DIM, 0, 0, 0, 1.f);
    gemm_kernel<true, true><<<gproj, 256>>>(h, wk, bk, k, N_TOK, C_DIM, C_DIM, 0, 0, 0, 1.f);
    gemm_kernel<true, true><<<gproj, 256>>>(h, wv, bv, v, N_TOK, C_DIM, C_DIM, 0, 0, 0, 1.f);

    // 3. scores = ALPHA * Q @ K^T   (batched NT, per-batch z)
    dim3 gsc(HW_DIM / BN, HW_DIM / BM, B_DIM);
    gemm_kernel<true, false><<<gsc, 256>>>(q, k, nullptr, s, HW_DIM, HW_DIM, C_DIM,
                                           (long long)HW_DIM * C_DIM,
                                           (long long)HW_DIM * C_DIM,
                                           (long long)HW_DIM * HW_DIM, ALPHA_V);

    // 4. softmax over keys
    softmax_kernel<<<N_TOK, 256>>>(s);

    // 5. attn_out = P @ V   (batched NN) -> reuse h
    dim3 gsv(C_DIM / BN, HW_DIM / BM, B_DIM);
    gemm_kernel<false, false><<<gsv, 256>>>(s, v, nullptr, h, HW_DIM, C_DIM, HW_DIM,
                                            (long long)HW_DIM * HW_DIM,
                                            (long long)HW_DIM * C_DIM,
                                            (long long)HW_DIM * C_DIM, 1.f);

    // 6. output projection -> reuse q
    gemm_kernel<true, true><<<gproj, 256>>>(h, wo, bo, q, N_TOK, C_DIM, C_DIM, 0, 0, 0, 1.f);

    // 7. transpose back to [B, C, 64, 64] + residual
    dim3 tb(32, 8);
    dim3 tg(HW_DIM / 32, C_DIM / 32, B_DIM);
    add_res_transpose_kernel<<<tg, tb>>>(q, x, out);
}

// round 9
// speedup vs baseline: 2.3238x; 2.3238x over previous
#include <cuda_runtime.h>
#include <cstdint>
#include <math.h>

#define C_DIM 512
#define HW_DIM 4096
#define B_DIM 8
#define N_TOK (B_DIM * HW_DIM)       // 32768 tokens
#define ALPHA_V 0.044194173824159216f
#define EPS_V 1e-6f

// ---------------- scratch (device globals: allocation-free) ----------------
__device__ float g_h[(size_t)N_TOK * C_DIM];                 // h (token-major), later attn_out
__device__ float g_q[(size_t)N_TOK * C_DIM];                 // q, later o_proj
__device__ float g_k[(size_t)N_TOK * C_DIM];
__device__ float g_v[(size_t)N_TOK * C_DIM];
__device__ float g_vt[(size_t)N_TOK * C_DIM];                // v transposed to [B][C][HW]
__device__ float g_s[(size_t)B_DIM * HW_DIM * HW_DIM];       // scores (512 MB)

// ---------------- tiny PTX helpers ----------------
__device__ __forceinline__ uint32_t smem_u32(const void* p) {
    uint32_t a;
    asm("{ .reg .u64 t; cvta.to.shared.u64 t, %1; cvt.u32.u64 %0, t; }" : "=r"(a) : "l"(p));
    return a;
}
#define CP_ASYNC16(dst, src) \
    asm volatile("cp.async.ca.shared.global [%0], [%1], 16;" :: "r"(dst), "l"(src) : "memory")
#define CP_COMMIT() asm volatile("cp.async.commit_group;" ::: "memory")
#define CP_WAIT1()  asm volatile("cp.async.wait_group 1;" ::: "memory")

// ---------------- GEMM config ----------------
// C[M,N] = alpha * A[M,K] @ B[N,K]^T + bias ; block tile 256x128, warp 64x64, BK=16
#define BMT 256
#define BNT 128
#define BKT 16
#define APITCH 20                         // floats per smem row (bank-bijective pad)
#define STAGES 3
#define A_STAGE_B (BMT * APITCH * 4)      // 20480
#define B_STAGE_B (BNT * APITCH * 4)      // 10240
#define STAGE_B   (A_STAGE_B + B_STAGE_B) // 30720
#define SM_BIAS_OFF 0
#define SM_TILE_OFF 512
#define SMEM_TOTAL (SM_TILE_OFF + STAGES * STAGE_B)   // 92672

template <bool HAS_BIAS>
__global__ __launch_bounds__(256, 1)
void mma_gemm(const float* __restrict__ A, const float* __restrict__ B,
              const float* __restrict__ bias, float* __restrict__ Cmat,
              int M, int N, int K,
              long long sA, long long sB, long long sC, float alpha) {
    extern __shared__ char smem[];
    const uint32_t sbase = smem_u32(smem);
    float* sbias = (float*)(smem + SM_BIAS_OFF);

    const int tid  = threadIdx.x;
    const int wid  = tid >> 5;
    const int lane = tid & 31;
    const int g    = lane >> 2;       // groupID (row within frag)
    const int t    = lane & 3;        // threadID_in_group (k within frag)
    const int wm   = (wid >> 1) * 64; // warp m offset
    const int wn   = (wid & 1) * 64;  // warp n offset

    const int m0 = blockIdx.y * BMT;
    const int n0 = blockIdx.x * BNT;
    const float* Ab = A + (size_t)blockIdx.z * sA + (size_t)m0 * K;
    const float* Bb = B + (size_t)blockIdx.z * sB + (size_t)n0 * K;
    float* Cb = Cmat + (size_t)blockIdx.z * sC;

    if (HAS_BIAS && tid < BNT) sbias[tid] = bias[n0 + tid];

    const int nk = K / BKT;

    // per-thread cp.async chunk coordinates
    // A: 1024 chunks (256 rows x 4 float4) -> 4/thread ; B: 512 -> 2/thread
    int arow[4], acol[4];
    #pragma unroll
    for (int i = 0; i < 4; i++) { int c = i * 256 + tid; arow[i] = c >> 2; acol[i] = c & 3; }
    int brow[2], bcol[2];
    #pragma unroll
    for (int i = 0; i < 2; i++) { int c = i * 256 + tid; brow[i] = c >> 2; bcol[i] = c & 3; }

    auto issue_stage = [&](int s, int kt) {
        const uint32_t ao = sbase + SM_TILE_OFF + s * STAGE_B;
        const uint32_t bo = ao + A_STAGE_B;
        const int k0 = kt * BKT;
        #pragma unroll
        for (int i = 0; i < 4; i++)
            CP_ASYNC16(ao + (arow[i] * APITCH + acol[i] * 4) * 4,
                       Ab + (size_t)arow[i] * K + k0 + acol[i] * 4);
        #pragma unroll
        for (int i = 0; i < 2; i++)
            CP_ASYNC16(bo + (brow[i] * APITCH + bcol[i] * 4) * 4,
                       Bb + (size_t)brow[i] * K + k0 + bcol[i] * 4);
    };

    float acc[4][8][4];
    #pragma unroll
    for (int f = 0; f < 4; f++)
        #pragma unroll
        for (int j = 0; j < 8; j++)
            #pragma unroll
            for (int r = 0; r < 4; r++) acc[f][j][r] = 0.f;

    // prologue: tiles 0 and 1 in flight
    issue_stage(0, 0); CP_COMMIT();
    issue_stage(1, 1); CP_COMMIT();

    for (int c = 0; c < nk; c++) {
        const int s = c % STAGES;
        CP_WAIT1();
        __syncthreads();

        // prefetch tile c+2 into stage (c+2)%STAGES (readers of that stage are done)
        if (c + 2 < nk) issue_stage((c + 2) % STAGES, c + 2);
        CP_COMMIT();

        const float* As = (const float*)(smem + SM_TILE_OFF + s * STAGE_B);
        const float* Bs = (const float*)(smem + SM_TILE_OFF + s * STAGE_B + A_STAGE_B);

        #pragma unroll
        for (int kk = 0; kk < BKT; kk += 8) {
            uint32_t af[4][4];
            #pragma unroll
            for (int f = 0; f < 4; f++) {
                const float* ap = As + (wm + f * 16 + g) * APITCH + kk + t;
                af[f][0] = __float_as_uint(ap[0]);
                af[f][1] = __float_as_uint(ap[8 * APITCH]);
                af[f][2] = __float_as_uint(ap[4]);
                af[f][3] = __float_as_uint(ap[8 * APITCH + 4]);
            }
            uint32_t bf[8][2];
            #pragma unroll
            for (int j = 0; j < 8; j++) {
                const float* bp = Bs + (wn + j * 8 + g) * APITCH + kk + t;
                bf[j][0] = __float_as_uint(bp[0]);
                bf[j][1] = __float_as_uint(bp[4]);
            }
            #pragma unroll
            for (int f = 0; f < 4; f++)
                #pragma unroll
                for (int j = 0; j < 8; j++)
                    asm volatile(
                        "mma.sync.aligned.m16n8k8.row.col.f32.tf32.tf32.f32 "
                        "{%0,%1,%2,%3}, {%4,%5,%6,%7}, {%8,%9}, {%0,%1,%2,%3};"
                        : "+f"(acc[f][j][0]), "+f"(acc[f][j][1]),
                          "+f"(acc[f][j][2]), "+f"(acc[f][j][3])
                        : "r"(af[f][0]), "r"(af[f][1]), "r"(af[f][2]), "r"(af[f][3]),
                          "r"(bf[j][0]), "r"(bf[j][1]));
        }
        __syncthreads();
    }

    // ---------------- epilogue ----------------
    #pragma unroll
    for (int f = 0; f < 4; f++) {
        const int r0 = m0 + wm + f * 16 + g;
        #pragma unroll
        for (int j = 0; j < 8; j++) {
            const int col = wn + j * 8 + 2 * t;
            float b0 = 0.f, b1 = 0.f;
            if (HAS_BIAS) { b0 = sbias[col]; b1 = sbias[col + 1]; }
            float2 lo, hi;
            lo.x = fmaf(acc[f][j][0], alpha, b0);
            lo.y = fmaf(acc[f][j][1], alpha, b1);
            hi.x = fmaf(acc[f][j][2], alpha, b0);
            hi.y = fmaf(acc[f][j][3], alpha, b1);
            *(float2*)&Cb[(size_t)r0 * N + n0 + col] = lo;
            *(float2*)&Cb[(size_t)(r0 + 8) * N + n0 + col] = hi;
        }
    }
}

// ---------------- reduction helpers ----------------
__inline__ __device__ float warpMax(float v) {
    #pragma unroll
    for (int o = 16; o > 0; o >>= 1) v = fmaxf(v, __shfl_xor_sync(0xffffffffu, v, o));
    return v;
}
__inline__ __device__ float warpSum(float v) {
    #pragma unroll
    for (int o = 16; o > 0; o >>= 1) v += __shfl_xor_sync(0xffffffffu, v, o);
    return v;
}

// ---------------- GroupNorm + transpose to token-major ----------------
__global__ void groupnorm_kernel(const float* __restrict__ x,
                                 const float* __restrict__ gamma,
                                 const float* __restrict__ beta,
                                 float* __restrict__ h) {
    const int b = blockIdx.x >> 5;
    const int g = blockIdx.x & 31;
    const float* xp = x + ((size_t)b * C_DIM + g * 16) * HW_DIM;
    const int tid = threadIdx.x;

    float s = 0.f, ss = 0.f;
    for (int i = tid; i < 16 * HW_DIM; i += 256) {
        float v = xp[i];
        s += v; ss += v * v;
    }
    __shared__ float r1[8], r2[8];
    float ws = warpSum(s), wss = warpSum(ss);
    if ((tid & 31) == 0) { r1[tid >> 5] = ws; r2[tid >> 5] = wss; }
    __syncthreads();
    __shared__ float s_mu, s_rs;
    if (tid == 0) {
        float S = 0.f, SS = 0.f;
        #pragma unroll
        for (int i = 0; i < 8; i++) { S += r1[i]; SS += r2[i]; }
        float mu = S * (1.f / 65536.f);
        float var = SS * (1.f / 65536.f) - mu * mu;
        s_mu = mu;
        s_rs = rsqrtf(var + EPS_V);
    }
    __syncthreads();
    const float mu = s_mu, rs = s_rs;

    for (int i = tid; i < 16 * HW_DIM; i += 256) {
        int cl = i >> 12;
        int hw = i & (HW_DIM - 1);
        int c = g * 16 + cl;
        float v = (xp[i] - mu) * rs * gamma[c] + beta[c];
        h[((size_t)b * HW_DIM + hw) * C_DIM + c] = v;
    }
}

// ---------------- row softmax over 4096 ----------------
__global__ void softmax_kernel(float* __restrict__ S) {
    float* p = S + (size_t)blockIdx.x * HW_DIM;
    const int tid = threadIdx.x;
    float v[16];
    float mx = -1e30f;
    #pragma unroll
    for (int i = 0; i < 16; i++) {
        v[i] = p[tid + i * 256];
        mx = fmaxf(mx, v[i]);
    }
    __shared__ float sm[8];
    float w = warpMax(mx);
    if ((tid & 31) == 0) sm[tid >> 5] = w;
    __syncthreads();
    if (tid < 32) {
        float tv = (tid < 8) ? sm[tid] : -1e30f;
        tv = warpMax(tv);
        if (tid == 0) sm[0] = tv;
    }
    __syncthreads();
    const float bm = sm[0];
    __syncthreads();

    float sum = 0.f;
    #pragma unroll
    for (int i = 0; i < 16; i++) {
        v[i] = __expf(v[i] - bm);
        sum += v[i];
    }
    float ws = warpSum(sum);
    if ((tid & 31) == 0) sm[tid >> 5] = ws;
    __syncthreads();
    if (tid < 32) {
        float tv = (tid < 8) ? sm[tid] : 0.f;
        tv = warpSum(tv);
        if (tid == 0) sm[0] = tv;
    }
    __syncthreads();
    const float inv = 1.0f / sm[0];
    #pragma unroll
    for (int i = 0; i < 16; i++) p[tid + i * 256] = v[i] * inv;
}

// ---------------- transpose [B][HW][C] -> [B][C][HW] ----------------
__global__ void transpose_kernel(const float* __restrict__ in, float* __restrict__ out) {
    __shared__ float t[32][33];
    const int b = blockIdx.z;
    const int hw0 = blockIdx.x * 32;
    const int c0 = blockIdx.y * 32;
    for (int r = threadIdx.y; r < 32; r += 8)
        t[r][threadIdx.x] = in[((size_t)b * HW_DIM + hw0 + r) * C_DIM + c0 + threadIdx.x];
    __syncthreads();
    for (int r = threadIdx.y; r < 32; r += 8)
        out[((size_t)b * C_DIM + c0 + r) * HW_DIM + hw0 + threadIdx.x] = t[threadIdx.x][r];
}

// ---------------- transpose back to [B,C,HW] + residual ----------------
__global__ void add_res_transpose_kernel(const float* __restrict__ op,
                                         const float* __restrict__ x,
                                         float* __restrict__ out) {
    __shared__ float t[32][33];
    const int b = blockIdx.z;
    const int hw0 = blockIdx.x * 32;
    const int c0 = blockIdx.y * 32;
    for (int r = threadIdx.y; r < 32; r += 8)
        t[r][threadIdx.x] = op[((size_t)b * HW_DIM + hw0 + r) * C_DIM + c0 + threadIdx.x];
    __syncthreads();
    for (int r = threadIdx.y; r < 32; r += 8) {
        int c = c0 + r;
        size_t idx = ((size_t)b * C_DIM + c) * HW_DIM + hw0 + threadIdx.x;
        out[idx] = t[threadIdx.x][r] + x[idx];
    }
}

// ---------------- launch ----------------
extern "C" void kernel_launch(void* const* d_in, const int* in_sizes, int n_in,
                              void* d_out, int out_size) {
    const float* x     = (const float*)d_in[0];
    const float* gamma = (const float*)d_in[1];
    const float* beta  = (const float*)d_in[2];
    const float* wq = (const float*)d_in[3]; const float* bq = (const float*)d_in[4];
    const float* wk = (const float*)d_in[5]; const float* bk = (const float*)d_in[6];
    const float* wv = (const float*)d_in[7]; const float* bv = (const float*)d_in[8];
    const float* wo = (const float*)d_in[9]; const float* bo = (const float*)d_in[10];
    float* out = (float*)d_out;

    float *h, *q, *k, *v, *vt, *s;
    cudaGetSymbolAddress((void**)&h, g_h);
    cudaGetSymbolAddress((void**)&q, g_q);
    cudaGetSymbolAddress((void**)&k, g_k);
    cudaGetSymbolAddress((void**)&v, g_v);
    cudaGetSymbolAddress((void**)&vt, g_vt);
    cudaGetSymbolAddress((void**)&s, g_s);

    cudaFuncSetAttribute(mma_gemm<true>,  cudaFuncAttributeMaxDynamicSharedMemorySize, SMEM_TOTAL);
    cudaFuncSetAttribute(mma_gemm<false>, cudaFuncAttributeMaxDynamicSharedMemorySize, SMEM_TOTAL);

    // 1. GroupNorm (+ transpose to token-major h)
    groupnorm_kernel<<<B_DIM * 32, 256>>>(x, gamma, beta, h);

    // 2. Q/K/V projections: [32768 x 512] = h @ W^T + b
    dim3 gproj(C_DIM / BNT, N_TOK / BMT, 1);
    mma_gemm<true><<<gproj, 256, SMEM_TOTAL>>>(h, wq, bq, q, N_TOK, C_DIM, C_DIM, 0, 0, 0, 1.f);
    mma_gemm<true><<<gproj, 256, SMEM_TOTAL>>>(h, wk, bk, k, N_TOK, C_DIM, C_DIM, 0, 0, 0, 1.f);
    mma_gemm<true><<<gproj, 256, SMEM_TOTAL>>>(h, wv, bv, v, N_TOK, C_DIM, C_DIM, 0, 0, 0, 1.f);

    // 3. transpose V to [B][C][HW] so P@V becomes NT
    dim3 tb(32, 8);
    dim3 tg(HW_DIM / 32, C_DIM / 32, B_DIM);
    transpose_kernel<<<tg, tb>>>(v, vt);

    // 4. scores = ALPHA * Q @ K^T (batched NT)
    dim3 gsc(HW_DIM / BNT, HW_DIM / BMT, B_DIM);
    mma_gemm<false><<<gsc, 256, SMEM_TOTAL>>>(q, k, nullptr, s, HW_DIM, HW_DIM, C_DIM,
                                              (long long)HW_DIM * C_DIM,
                                              (long long)HW_DIM * C_DIM,
                                              (long long)HW_DIM * HW_DIM, ALPHA_V);

    // 5. softmax over keys
    softmax_kernel<<<N_TOK, 256>>>(s);

    // 6. attn_out = P @ Vt^T (batched NT) -> reuse h
    dim3 gsv(C_DIM / BNT, HW_DIM / BMT, B_DIM);
    mma_gemm<false><<<gsv, 256, SMEM_TOTAL>>>(s, vt, nullptr, h, HW_DIM, C_DIM, HW_DIM,
                                              (long long)HW_DIM * HW_DIM,
                                              (long long)C_DIM * HW_DIM,
                                              (long long)HW_DIM * C_DIM, 1.f);

    // 7. output projection -> reuse q
    mma_gemm<true><<<gproj, 256, SMEM_TOTAL>>>(h, wo, bo, q, N_TOK, C_DIM, C_DIM, 0, 0, 0, 1.f);

    // 8. transpose back to [B, C, 64, 64] + residual
    add_res_transpose_kernel<<<tg, tb>>>(q, x, out);
}

// round 12
// speedup vs baseline: 2.3508x; 1.0116x over previous
#include <cuda_runtime.h>
#include <cstdint>
#include <math.h>

#define C_DIM 512
#define HW_DIM 4096
#define B_DIM 8
#define N_TOK (B_DIM * HW_DIM)       // 32768 tokens
#define ALPHA_V 0.044194173824159216f
#define EPS_V 1e-6f

// ---------------- scratch (device globals: allocation-free) ----------------
__device__ float g_h[(size_t)N_TOK * C_DIM];                 // h (token-major), later attn_out
__device__ float g_q[(size_t)N_TOK * C_DIM];                 // q, later o_proj
__device__ float g_k[(size_t)N_TOK * C_DIM];
__device__ float g_v[(size_t)N_TOK * C_DIM];
__device__ float g_vt[(size_t)N_TOK * C_DIM];                // v transposed to [B][C][HW]
__device__ float g_s[(size_t)B_DIM * HW_DIM * HW_DIM];       // scores (512 MB)

// ---------------- tiny PTX helpers ----------------
__device__ __forceinline__ uint32_t smem_u32(const void* p) {
    uint32_t a;
    asm("{ .reg .u64 t; cvta.to.shared.u64 t, %1; cvt.u32.u64 %0, t; }" : "=r"(a) : "l"(p));
    return a;
}
#define CP_ASYNC16(dst, src) \
    asm volatile("cp.async.ca.shared.global [%0], [%1], 16;" :: "r"(dst), "l"(src) : "memory")
#define CP_COMMIT() asm volatile("cp.async.commit_group;" ::: "memory")
#define CP_WAIT2()  asm volatile("cp.async.wait_group 2;" ::: "memory")

// ---------------- GEMM config ----------------
// C[M,N] = alpha * A[M,K] @ B[N,K]^T + bias
// block tile 128x128, 8 warps in 4x2 grid, warp tile 32x64, BK=16, 4 stages
#define BMT 128
#define BNT 128
#define BKT 16
#define APITCH 20                         // floats per smem row (bank-bijective pad)
#define STAGES 4
#define A_STAGE_B (BMT * APITCH * 4)      // 10240
#define B_STAGE_B (BNT * APITCH * 4)      // 10240
#define STAGE_B   (A_STAGE_B + B_STAGE_B) // 20480
#define SM_BIAS_OFF 0
#define SM_TILE_OFF 512
#define SMEM_TOTAL (SM_TILE_OFF + STAGES * STAGE_B)   // 82432 -> 2 CTAs/SM

template <bool HAS_BIAS>
__global__ __launch_bounds__(256, 2)
void mma_gemm(const float* __restrict__ A, const float* __restrict__ B,
              const float* __restrict__ bias, float* __restrict__ Cmat,
              int M, int N, int K,
              long long sA, long long sB, long long sC, float alpha) {
    extern __shared__ char smem[];
    const uint32_t sbase = smem_u32(smem);
    float* sbias = (float*)(smem + SM_BIAS_OFF);

    const int tid  = threadIdx.x;
    const int wid  = tid >> 5;
    const int lane = tid & 31;
    const int g    = lane >> 2;       // groupID (row within frag)
    const int t    = lane & 3;        // threadID_in_group (k within frag)
    const int wm   = (wid >> 1) * 32; // warp m offset (4 rows of warps)
    const int wn   = (wid & 1) * 64;  // warp n offset (2 cols of warps)

    const int m0 = blockIdx.y * BMT;
    const int n0 = blockIdx.x * BNT;
    const float* Ab = A + (size_t)blockIdx.z * sA + (size_t)m0 * K;
    const float* Bb = B + (size_t)blockIdx.z * sB + (size_t)n0 * K;
    float* Cb = Cmat + (size_t)blockIdx.z * sC;

    if (HAS_BIAS && tid < BNT) sbias[tid] = bias[n0 + tid];

    const int nk = K / BKT;

    // per-thread cp.async chunk coordinates: A 512 chunks -> 2/thread, B same
    int arow[2], acol[2];
    #pragma unroll
    for (int i = 0; i < 2; i++) { int c = i * 256 + tid; arow[i] = c >> 2; acol[i] = c & 3; }

    auto issue_stage = [&](int s, int kt) {
        const uint32_t ao = sbase + SM_TILE_OFF + s * STAGE_B;
        const uint32_t bo = ao + A_STAGE_B;
        const int k0 = kt * BKT;
        #pragma unroll
        for (int i = 0; i < 2; i++) {
            CP_ASYNC16(ao + (arow[i] * APITCH + acol[i] * 4) * 4,
                       Ab + (size_t)arow[i] * K + k0 + acol[i] * 4);
            CP_ASYNC16(bo + (arow[i] * APITCH + acol[i] * 4) * 4,
                       Bb + (size_t)arow[i] * K + k0 + acol[i] * 4);
        }
    };

    float acc[2][8][4];
    #pragma unroll
    for (int f = 0; f < 2; f++)
        #pragma unroll
        for (int j = 0; j < 8; j++)
            #pragma unroll
            for (int r = 0; r < 4; r++) acc[f][j][r] = 0.f;

    // prologue: 3 tiles in flight
    issue_stage(0, 0); CP_COMMIT();
    issue_stage(1, 1); CP_COMMIT();
    issue_stage(2, 2); CP_COMMIT();

    for (int c = 0; c < nk; c++) {
        const int s = c & (STAGES - 1);
        CP_WAIT2();              // stage c landed (<=2 younger groups in flight)
        __syncthreads();         // all warps done with stage (c-1); stage c visible

        if (c + 3 < nk) issue_stage((c + 3) & (STAGES - 1), c + 3);
        CP_COMMIT();

        const float* As = (const float*)(smem + SM_TILE_OFF + s * STAGE_B);
        const float* Bs = (const float*)(smem + SM_TILE_OFF + s * STAGE_B + A_STAGE_B);

        #pragma unroll
        for (int kk = 0; kk < BKT; kk += 8) {
            uint32_t af[2][4];
            #pragma unroll
            for (int f = 0; f < 2; f++) {
                const float* ap = As + (wm + f * 16 + g) * APITCH + kk + t;
                af[f][0] = __float_as_uint(ap[0]);
                af[f][1] = __float_as_uint(ap[8 * APITCH]);
                af[f][2] = __float_as_uint(ap[4]);
                af[f][3] = __float_as_uint(ap[8 * APITCH + 4]);
            }
            uint32_t bf[8][2];
            #pragma unroll
            for (int j = 0; j < 8; j++) {
                const float* bp = Bs + (wn + j * 8 + g) * APITCH + kk + t;
                bf[j][0] = __float_as_uint(bp[0]);
                bf[j][1] = __float_as_uint(bp[4]);
            }
            #pragma unroll
            for (int f = 0; f < 2; f++)
                #pragma unroll
                for (int j = 0; j < 8; j++)
                    asm volatile(
                        "mma.sync.aligned.m16n8k8.row.col.f32.tf32.tf32.f32 "
                        "{%0,%1,%2,%3}, {%4,%5,%6,%7}, {%8,%9}, {%0,%1,%2,%3};"
                        : "+f"(acc[f][j][0]), "+f"(acc[f][j][1]),
                          "+f"(acc[f][j][2]), "+f"(acc[f][j][3])
                        : "r"(af[f][0]), "r"(af[f][1]), "r"(af[f][2]), "r"(af[f][3]),
                          "r"(bf[j][0]), "r"(bf[j][1]));
        }
    }

    // ---------------- epilogue ----------------
    #pragma unroll
    for (int f = 0; f < 2; f++) {
        const int r0 = m0 + wm + f * 16 + g;
        #pragma unroll
        for (int j = 0; j < 8; j++) {
            const int col = wn + j * 8 + 2 * t;
            float b0 = 0.f, b1 = 0.f;
            if (HAS_BIAS) { b0 = sbias[col]; b1 = sbias[col + 1]; }
            float2 lo, hi;
            lo.x = fmaf(acc[f][j][0], alpha, b0);
            lo.y = fmaf(acc[f][j][1], alpha, b1);
            hi.x = fmaf(acc[f][j][2], alpha, b0);
            hi.y = fmaf(acc[f][j][3], alpha, b1);
            *(float2*)&Cb[(size_t)r0 * N + n0 + col] = lo;
            *(float2*)&Cb[(size_t)(r0 + 8) * N + n0 + col] = hi;
        }
    }
}

// ---------------- reduction helpers ----------------
__inline__ __device__ float warpMax(float v) {
    #pragma unroll
    for (int o = 16; o > 0; o >>= 1) v = fmaxf(v, __shfl_xor_sync(0xffffffffu, v, o));
    return v;
}
__inline__ __device__ float warpSum(float v) {
    #pragma unroll
    for (int o = 16; o > 0; o >>= 1) v += __shfl_xor_sync(0xffffffffu, v, o);
    return v;
}

// ---------------- GroupNorm + transpose to token-major ----------------
__global__ void groupnorm_kernel(const float* __restrict__ x,
                                 const float* __restrict__ gamma,
                                 const float* __restrict__ beta,
                                 float* __restrict__ h) {
    const int b = blockIdx.x >> 5;
    const int g = blockIdx.x & 31;
    const float* xp = x + ((size_t)b * C_DIM + g * 16) * HW_DIM;
    const int tid = threadIdx.x;

    float s = 0.f, ss = 0.f;
    for (int i = tid; i < 16 * HW_DIM; i += 256) {
        float v = xp[i];
        s += v; ss += v * v;
    }
    __shared__ float r1[8], r2[8];
    float ws = warpSum(s), wss = warpSum(ss);
    if ((tid & 31) == 0) { r1[tid >> 5] = ws; r2[tid >> 5] = wss; }
    __syncthreads();
    __shared__ float s_mu, s_rs;
    if (tid == 0) {
        float S = 0.f, SS = 0.f;
        #pragma unroll
        for (int i = 0; i < 8; i++) { S += r1[i]; SS += r2[i]; }
        float mu = S * (1.f / 65536.f);
        float var = SS * (1.f / 65536.f) - mu * mu;
        s_mu = mu;
        s_rs = rsqrtf(var + EPS_V);
    }
    __syncthreads();
    const float mu = s_mu, rs = s_rs;

    for (int i = tid; i < 16 * HW_DIM; i += 256) {
        int cl = i >> 12;
        int hw = i & (HW_DIM - 1);
        int c = g * 16 + cl;
        float v = (xp[i] - mu) * rs * gamma[c] + beta[c];
        h[((size_t)b * HW_DIM + hw) * C_DIM + c] = v;
    }
}

// ---------------- row softmax over 4096 ----------------
__global__ void softmax_kernel(float* __restrict__ S) {
    float* p = S + (size_t)blockIdx.x * HW_DIM;
    const int tid = threadIdx.x;
    float v[16];
    float mx = -1e30f;
    #pragma unroll
    for (int i = 0; i < 16; i++) {
        v[i] = p[tid + i * 256];
        mx = fmaxf(mx, v[i]);
    }
    __shared__ float sm[8];
    float w = warpMax(mx);
    if ((tid & 31) == 0) sm[tid >> 5] = w;
    __syncthreads();
    if (tid < 32) {
        float tv = (tid < 8) ? sm[tid] : -1e30f;
        tv = warpMax(tv);
        if (tid == 0) sm[0] = tv;
    }
    __syncthreads();
    const float bm = sm[0];
    __syncthreads();

    float sum = 0.f;
    #pragma unroll
    for (int i = 0; i < 16; i++) {
        v[i] = __expf(v[i] - bm);
        sum += v[i];
    }
    float ws = warpSum(sum);
    if ((tid & 31) == 0) sm[tid >> 5] = ws;
    __syncthreads();
    if (tid < 32) {
        float tv = (tid < 8) ? sm[tid] : 0.f;
        tv = warpSum(tv);
        if (tid == 0) sm[0] = tv;
    }
    __syncthreads();
    const float inv = 1.0f / sm[0];
    #pragma unroll
    for (int i = 0; i < 16; i++) p[tid + i * 256] = v[i] * inv;
}

// ---------------- transpose [B][HW][C] -> [B][C][HW] ----------------
__global__ void transpose_kernel(const float* __restrict__ in, float* __restrict__ out) {
    __shared__ float t[32][33];
    const int b = blockIdx.z;
    const int hw0 = blockIdx.x * 32;
    const int c0 = blockIdx.y * 32;
    for (int r = threadIdx.y; r < 32; r += 8)
        t[r][threadIdx.x] = in[((size_t)b * HW_DIM + hw0 + r) * C_DIM + c0 + threadIdx.x];
    __syncthreads();
    for (int r = threadIdx.y; r < 32; r += 8)
        out[((size_t)b * C_DIM + c0 + r) * HW_DIM + hw0 + threadIdx.x] = t[threadIdx.x][r];
}

// ---------------- transpose back to [B,C,HW] + residual ----------------
__global__ void add_res_transpose_kernel(const float* __restrict__ op,
                                         const float* __restrict__ x,
                                         float* __restrict__ out) {
    __shared__ float t[32][33];
    const int b = blockIdx.z;
    const int hw0 = blockIdx.x * 32;
    const int c0 = blockIdx.y * 32;
    for (int r = threadIdx.y; r < 32; r += 8)
        t[r][threadIdx.x] = op[((size_t)b * HW_DIM + hw0 + r) * C_DIM + c0 + threadIdx.x];
    __syncthreads();
    for (int r = threadIdx.y; r < 32; r += 8) {
        int c = c0 + r;
        size_t idx = ((size_t)b * C_DIM + c) * HW_DIM + hw0 + threadIdx.x;
        out[idx] = t[threadIdx.x][r] + x[idx];
    }
}

// ---------------- launch ----------------
extern "C" void kernel_launch(void* const* d_in, const int* in_sizes, int n_in,
                              void* d_out, int out_size) {
    const float* x     = (const float*)d_in[0];
    const float* gamma = (const float*)d_in[1];
    const float* beta  = (const float*)d_in[2];
    const float* wq = (const float*)d_in[3]; const float* bq = (const float*)d_in[4];
    const float* wk = (const float*)d_in[5]; const float* bk = (const float*)d_in[6];
    const float* wv = (const float*)d_in[7]; const float* bv = (const float*)d_in[8];
    const float* wo = (const float*)d_in[9]; const float* bo = (const float*)d_in[10];
    float* out = (float*)d_out;

    float *h, *q, *k, *v, *vt, *s;
    cudaGetSymbolAddress((void**)&h, g_h);
    cudaGetSymbolAddress((void**)&q, g_q);
    cudaGetSymbolAddress((void**)&k, g_k);
    cudaGetSymbolAddress((void**)&v, g_v);
    cudaGetSymbolAddress((void**)&vt, g_vt);
    cudaGetSymbolAddress((void**)&s, g_s);

    cudaFuncSetAttribute(mma_gemm<true>,  cudaFuncAttributeMaxDynamicSharedMemorySize, SMEM_TOTAL);
    cudaFuncSetAttribute(mma_gemm<false>, cudaFuncAttributeMaxDynamicSharedMemorySize, SMEM_TOTAL);

    // 1. GroupNorm (+ transpose to token-major h)
    groupnorm_kernel<<<B_DIM * 32, 256>>>(x, gamma, beta, h);

    // 2. Q/K/V projections: [32768 x 512] = h @ W^T + b
    dim3 gproj(C_DIM / BNT, N_TOK / BMT, 1);
    mma_gemm<true><<<gproj, 256, SMEM_TOTAL>>>(h, wq, bq, q, N_TOK, C_DIM, C_DIM, 0, 0, 0, 1.f);
    mma_gemm<true><<<gproj, 256, SMEM_TOTAL>>>(h, wk, bk, k, N_TOK, C_DIM, C_DIM, 0, 0, 0, 1.f);
    mma_gemm<true><<<gproj, 256, SMEM_TOTAL>>>(h, wv, bv, v, N_TOK, C_DIM, C_DIM, 0, 0, 0, 1.f);

    // 3. transpose V to [B][C][HW] so P@V becomes NT
    dim3 tb(32, 8);
    dim3 tg(HW_DIM / 32, C_DIM / 32, B_DIM);
    transpose_kernel<<<tg, tb>>>(v, vt);

    // 4. scores = ALPHA * Q @ K^T (batched NT)
    dim3 gsc(HW_DIM / BNT, HW_DIM / BMT, B_DIM);
    mma_gemm<false><<<gsc, 256, SMEM_TOTAL>>>(q, k, nullptr, s, HW_DIM, HW_DIM, C_DIM,
                                              (long long)HW_DIM * C_DIM,
                                              (long long)HW_DIM * C_DIM,
                                              (long long)HW_DIM * HW_DIM, ALPHA_V);

    // 5. softmax over keys
    softmax_kernel<<<N_TOK, 256>>>(s);

    // 6. attn_out = P @ Vt^T (batched NT) -> reuse h
    dim3 gsv(C_DIM / BNT, HW_DIM / BMT, B_DIM);
    mma_gemm<false><<<gsv, 256, SMEM_TOTAL>>>(s, vt, nullptr, h, HW_DIM, C_DIM, HW_DIM,
                                              (long long)HW_DIM * HW_DIM,
                                              (long long)C_DIM * HW_DIM,
                                              (long long)HW_DIM * C_DIM, 1.f);

    // 7. output projection -> reuse q
    mma_gemm<true><<<gproj, 256, SMEM_TOTAL>>>(h, wo, bo, q, N_TOK, C_DIM, C_DIM, 0, 0, 0, 1.f);

    // 8. transpose back to [B, C, 64, 64] + residual
    add_res_transpose_kernel<<<tg, tb>>>(q, x, out);
}

// round 17
// speedup vs baseline: 4.8144x; 2.0480x over previous
#include <cuda_runtime.h>
#include <cuda_fp16.h>
#include <cstdint>
#include <math.h>

#define C_DIM 512
#define HW_DIM 4096
#define B_DIM 8
#define N_TOK (B_DIM * HW_DIM)       // 32768 tokens
#define ALPHA_V 0.044194173824159216f
#define EPS_V 1e-6f

// ---------------- scratch (device globals: allocation-free) ----------------
__device__ __half g_h16[(size_t)N_TOK * C_DIM];               // GN output / later attn_out
__device__ __half g_q16[(size_t)N_TOK * C_DIM];
__device__ __half g_k16[(size_t)N_TOK * C_DIM];
__device__ __half g_v16[(size_t)N_TOK * C_DIM];
__device__ __half g_vt16[(size_t)N_TOK * C_DIM];              // v transposed [B][C][HW]
__device__ __half g_s16[(size_t)B_DIM * HW_DIM * HW_DIM];     // scores/P (256 MB)
__device__ __half g_w16[(size_t)4 * C_DIM * C_DIM];           // wq,wk,wv,wo fp16
__device__ float  g_o32[(size_t)N_TOK * C_DIM];               // o-proj fp32 output

// ---------------- tiny PTX helpers ----------------
__device__ __forceinline__ uint32_t smem_u32(const void* p) {
    uint32_t a;
    asm("{ .reg .u64 t; cvta.to.shared.u64 t, %1; cvt.u32.u64 %0, t; }" : "=r"(a) : "l"(p));
    return a;
}
#define CP_ASYNC16(dst, src) \
    asm volatile("cp.async.ca.shared.global [%0], [%1], 16;" :: "r"(dst), "l"(src) : "memory")
#define CP_COMMIT() asm volatile("cp.async.commit_group;" ::: "memory")
#define CP_WAIT2()  asm volatile("cp.async.wait_group 2;" ::: "memory")
#define LDMATRIX_X4(r0, r1, r2, r3, addr) \
    asm volatile("ldmatrix.sync.aligned.m8n8.x4.shared.b16 {%0,%1,%2,%3}, [%4];" \
        : "=r"(r0), "=r"(r1), "=r"(r2), "=r"(r3) : "r"(addr))

// ---------------- GEMM config ----------------
// C[M,N] = alpha * A[M,K] @ B[N,K]^T + bias ; A,B fp16 K-major, acc fp32
// block tile 128x128, 8 warps 4x2, warp tile 32x64, BK=32 halves, 4 stages
#define BMT 128
#define BNT 128
#define BKH 32                             // K per chunk (halves)
#define PITCH_B 80                         // bytes per smem row (40 halves): (5r+c)%8 bijective
#define STAGES 4
#define A_STAGE_B (BMT * PITCH_B)          // 10240
#define B_STAGE_B (BNT * PITCH_B)          // 10240
#define STAGE_B   (A_STAGE_B + B_STAGE_B)  // 20480
#define SM_BIAS_OFF 0
#define SM_TILE_OFF 512
#define SMEM_TOTAL (SM_TILE_OFF + STAGES * STAGE_B)   // 82432 -> 2 CTAs/SM

template <bool HAS_BIAS, bool OUT_HALF>
__global__ __launch_bounds__(256, 2)
void mma_gemm_h(const __half* __restrict__ A, const __half* __restrict__ B,
                const float* __restrict__ bias, void* __restrict__ Cmat,
                int M, int N, int K,
                long long sA, long long sB, long long sC, float alpha) {
    extern __shared__ char smem[];
    const uint32_t sbase = smem_u32(smem);
    float* sbias = (float*)(smem + SM_BIAS_OFF);

    const int tid  = threadIdx.x;
    const int wid  = tid >> 5;
    const int lane = tid & 31;
    const int g    = lane >> 2;        // groupID
    const int t    = lane & 3;         // thread in group
    const int wm   = (wid >> 1) * 32;  // warp m offset
    const int wn   = (wid & 1) * 64;   // warp n offset

    const int m0 = blockIdx.y * BMT;
    const int n0 = blockIdx.x * BNT;
    const __half* Ab = A + (size_t)blockIdx.z * sA + (size_t)m0 * K;
    const __half* Bb = B + (size_t)blockIdx.z * sB + (size_t)n0 * K;

    if (HAS_BIAS && tid < BNT) sbias[tid] = bias[n0 + tid];

    const int nk = K / BKH;

    // cp.async chunk coords: tile = 128 rows x 4 x 16B; 512 chunks; 2/thread (A and B)
    int arow[2], acol[2];
    #pragma unroll
    for (int i = 0; i < 2; i++) { int c = i * 256 + tid; arow[i] = c >> 2; acol[i] = c & 3; }

    auto issue_stage = [&](int s, int kt) {
        const uint32_t ao = sbase + SM_TILE_OFF + s * STAGE_B;
        const uint32_t bo = ao + A_STAGE_B;
        const int k0 = kt * BKH;
        #pragma unroll
        for (int i = 0; i < 2; i++) {
            CP_ASYNC16(ao + arow[i] * PITCH_B + acol[i] * 16,
                       Ab + (size_t)arow[i] * K + k0 + acol[i] * 8);
            CP_ASYNC16(bo + arow[i] * PITCH_B + acol[i] * 16,
                       Bb + (size_t)arow[i] * K + k0 + acol[i] * 8);
        }
    };

    // ldmatrix per-thread byte offsets within a tile (k-step adds kk*2)
    // A: rows m .. m+15 (lanes 0-15 -> +lane&15), k group = (lane>>4)*8
    const uint32_t aoff = (uint32_t)(wm + (lane & 15)) * PITCH_B + ((lane >> 4) << 4);
    // B: rows n + (lane&7) + ((lane>>4)*8), k group = ((lane>>3)&1)*8
    const uint32_t boff = (uint32_t)(wn + (lane & 7) + ((lane >> 4) << 3)) * PITCH_B
                        + (((lane >> 3) & 1) << 4);

    float acc[2][8][4];
    #pragma unroll
    for (int f = 0; f < 2; f++)
        #pragma unroll
        for (int j = 0; j < 8; j++)
            #pragma unroll
            for (int r = 0; r < 4; r++) acc[f][j][r] = 0.f;

    issue_stage(0, 0); CP_COMMIT();
    issue_stage(1, 1); CP_COMMIT();
    issue_stage(2, 2); CP_COMMIT();

    for (int c = 0; c < nk; c++) {
        const int s = c & (STAGES - 1);
        CP_WAIT2();
        __syncthreads();

        if (c + 3 < nk) issue_stage((c + 3) & (STAGES - 1), c + 3);
        CP_COMMIT();

        const uint32_t abase = sbase + SM_TILE_OFF + s * STAGE_B;
        const uint32_t bbase = abase + A_STAGE_B;

        #pragma unroll
        for (int kk = 0; kk < BKH; kk += 16) {
            uint32_t af[2][4];
            #pragma unroll
            for (int f = 0; f < 2; f++)
                LDMATRIX_X4(af[f][0], af[f][1], af[f][2], af[f][3],
                            abase + aoff + f * 16 * PITCH_B + kk * 2);
            uint32_t bf[8][2];
            #pragma unroll
            for (int j2 = 0; j2 < 4; j2++)
                LDMATRIX_X4(bf[2 * j2][0], bf[2 * j2][1], bf[2 * j2 + 1][0], bf[2 * j2 + 1][1],
                            bbase + boff + j2 * 16 * PITCH_B + kk * 2);
            #pragma unroll
            for (int f = 0; f < 2; f++)
                #pragma unroll
                for (int j = 0; j < 8; j++)
                    asm volatile(
                        "mma.sync.aligned.m16n8k16.row.col.f32.f16.f16.f32 "
                        "{%0,%1,%2,%3}, {%4,%5,%6,%7}, {%8,%9}, {%0,%1,%2,%3};"
                        : "+f"(acc[f][j][0]), "+f"(acc[f][j][1]),
                          "+f"(acc[f][j][2]), "+f"(acc[f][j][3])
                        : "r"(af[f][0]), "r"(af[f][1]), "r"(af[f][2]), "r"(af[f][3]),
                          "r"(bf[j][0]), "r"(bf[j][1]));
        }
    }

    // ---------------- epilogue ----------------
    #pragma unroll
    for (int f = 0; f < 2; f++) {
        const int r0 = m0 + wm + f * 16 + g;
        #pragma unroll
        for (int j = 0; j < 8; j++) {
            const int col = wn + j * 8 + 2 * t;
            float b0 = 0.f, b1 = 0.f;
            if (HAS_BIAS) { b0 = sbias[col]; b1 = sbias[col + 1]; }
            float v00 = fmaf(acc[f][j][0], alpha, b0);
            float v01 = fmaf(acc[f][j][1], alpha, b1);
            float v10 = fmaf(acc[f][j][2], alpha, b0);
            float v11 = fmaf(acc[f][j][3], alpha, b1);
            if (OUT_HALF) {
                __half* Cb = (__half*)Cmat + (size_t)blockIdx.z * sC;
                *(__half2*)&Cb[(size_t)r0 * N + n0 + col] = __floats2half2_rn(v00, v01);
                *(__half2*)&Cb[(size_t)(r0 + 8) * N + n0 + col] = __floats2half2_rn(v10, v11);
            } else {
                float* Cb = (float*)Cmat + (size_t)blockIdx.z * sC;
                *(float2*)&Cb[(size_t)r0 * N + n0 + col] = make_float2(v00, v01);
                *(float2*)&Cb[(size_t)(r0 + 8) * N + n0 + col] = make_float2(v10, v11);
            }
        }
    }
}

// ---------------- reduction helpers ----------------
__inline__ __device__ float warpMax(float v) {
    #pragma unroll
    for (int o = 16; o > 0; o >>= 1) v = fmaxf(v, __shfl_xor_sync(0xffffffffu, v, o));
    return v;
}
__inline__ __device__ float warpSum(float v) {
    #pragma unroll
    for (int o = 16; o > 0; o >>= 1) v += __shfl_xor_sync(0xffffffffu, v, o);
    return v;
}

// ---------------- GroupNorm + transpose to token-major (fp16 out) ----------------
__global__ void groupnorm_kernel(const float* __restrict__ x,
                                 const float* __restrict__ gamma,
                                 const float* __restrict__ beta,
                                 __half* __restrict__ h) {
    const int b = blockIdx.x >> 5;
    const int g = blockIdx.x & 31;
    const float* xp = x + ((size_t)b * C_DIM + g * 16) * HW_DIM;
    const int tid = threadIdx.x;

    float s = 0.f, ss = 0.f;
    for (int i = tid; i < 16 * HW_DIM; i += 256) {
        float v = xp[i];
        s += v; ss += v * v;
    }
    __shared__ float r1[8], r2[8];
    float ws = warpSum(s), wss = warpSum(ss);
    if ((tid & 31) == 0) { r1[tid >> 5] = ws; r2[tid >> 5] = wss; }
    __syncthreads();
    __shared__ float s_mu, s_rs;
    if (tid == 0) {
        float S = 0.f, SS = 0.f;
        #pragma unroll
        for (int i = 0; i < 8; i++) { S += r1[i]; SS += r2[i]; }
        float mu = S * (1.f / 65536.f);
        float var = SS * (1.f / 65536.f) - mu * mu;
        s_mu = mu;
        s_rs = rsqrtf(var + EPS_V);
    }
    __syncthreads();
    const float mu = s_mu, rs = s_rs;

    for (int i = tid; i < 16 * HW_DIM; i += 256) {
        int cl = i >> 12;
        int hw = i & (HW_DIM - 1);
        int c = g * 16 + cl;
        float v = (xp[i] - mu) * rs * gamma[c] + beta[c];
        h[((size_t)b * HW_DIM + hw) * C_DIM + c] = __float2half_rn(v);
    }
}

// ---------------- fp32 -> fp16 convert ----------------
__global__ void f2h_kernel(const float* __restrict__ src, __half* __restrict__ dst, int n) {
    int i = (blockIdx.x * 256 + threadIdx.x) * 4;
    if (i < n) {
        float4 f = *(const float4*)(src + i);
        __half2* d = (__half2*)(dst + i);
        d[0] = __floats2half2_rn(f.x, f.y);
        d[1] = __floats2half2_rn(f.z, f.w);
    }
}

// ---------------- row softmax over 4096 (fp16 in/out, fp32 math) ----------------
__global__ void softmax_h_kernel(__half* __restrict__ S) {
    __half2* p = (__half2*)(S + (size_t)blockIdx.x * HW_DIM);
    const int tid = threadIdx.x;
    float2 v[8];
    float mx = -1e30f;
    #pragma unroll
    for (int i = 0; i < 8; i++) {
        v[i] = __half22float2(p[tid + i * 256]);
        mx = fmaxf(mx, fmaxf(v[i].x, v[i].y));
    }
    __shared__ float sm[8];
    float w = warpMax(mx);
    if ((tid & 31) == 0) sm[tid >> 5] = w;
    __syncthreads();
    if (tid < 32) {
        float tv = (tid < 8) ? sm[tid] : -1e30f;
        tv = warpMax(tv);
        if (tid == 0) sm[0] = tv;
    }
    __syncthreads();
    const float bm = sm[0];
    __syncthreads();

    float sum = 0.f;
    #pragma unroll
    for (int i = 0; i < 8; i++) {
        v[i].x = __expf(v[i].x - bm);
        v[i].y = __expf(v[i].y - bm);
        sum += v[i].x + v[i].y;
    }
    float ws = warpSum(sum);
    if ((tid & 31) == 0) sm[tid >> 5] = ws;
    __syncthreads();
    if (tid < 32) {
        float tv = (tid < 8) ? sm[tid] : 0.f;
        tv = warpSum(tv);
        if (tid == 0) sm[0] = tv;
    }
    __syncthreads();
    const float inv = 1.0f / sm[0];
    #pragma unroll
    for (int i = 0; i < 8; i++)
        p[tid + i * 256] = __floats2half2_rn(v[i].x * inv, v[i].y * inv);
}

// ---------------- transpose fp16 [B][HW][C] -> [B][C][HW] ----------------
__global__ void transpose_h_kernel(const __half* __restrict__ in, __half* __restrict__ out) {
    __shared__ __half t[32][34];
    const int b = blockIdx.z;
    const int hw0 = blockIdx.x * 32;
    const int c0 = blockIdx.y * 32;
    for (int r = threadIdx.y; r < 32; r += 8)
        t[r][threadIdx.x] = in[((size_t)b * HW_DIM + hw0 + r) * C_DIM + c0 + threadIdx.x];
    __syncthreads();
    for (int r = threadIdx.y; r < 32; r += 8)
        out[((size_t)b * C_DIM + c0 + r) * HW_DIM + hw0 + threadIdx.x] = t[threadIdx.x][r];
}

// ---------------- transpose back to [B,C,HW] + residual (fp32) ----------------
__global__ void add_res_transpose_kernel(const float* __restrict__ op,
                                         const float* __restrict__ x,
                                         float* __restrict__ out) {
    __shared__ float t[32][33];
    const int b = blockIdx.z;
    const int hw0 = blockIdx.x * 32;
    const int c0 = blockIdx.y * 32;
    for (int r = threadIdx.y; r < 32; r += 8)
        t[r][threadIdx.x] = op[((size_t)b * HW_DIM + hw0 + r) * C_DIM + c0 + threadIdx.x];
    __syncthreads();
    for (int r = threadIdx.y; r < 32; r += 8) {
        int c = c0 + r;
        size_t idx = ((size_t)b * C_DIM + c) * HW_DIM + hw0 + threadIdx.x;
        out[idx] = t[threadIdx.x][r] + x[idx];
    }
}

// ---------------- launch ----------------
extern "C" void kernel_launch(void* const* d_in, const int* in_sizes, int n_in,
                              void* d_out, int out_size) {
    const float* x     = (const float*)d_in[0];
    const float* gamma = (const float*)d_in[1];
    const float* beta  = (const float*)d_in[2];
    const float* wq = (const float*)d_in[3]; const float* bq = (const float*)d_in[4];
    const float* wk = (const float*)d_in[5]; const float* bk = (const float*)d_in[6];
    const float* wv = (const float*)d_in[7]; const float* bv = (const float*)d_in[8];
    const float* wo = (const float*)d_in[9]; const float* bo = (const float*)d_in[10];
    float* out = (float*)d_out;

    __half *h16, *q16, *k16, *v16, *vt16, *s16, *w16;
    float* o32;
    cudaGetSymbolAddress((void**)&h16, g_h16);
    cudaGetSymbolAddress((void**)&q16, g_q16);
    cudaGetSymbolAddress((void**)&k16, g_k16);
    cudaGetSymbolAddress((void**)&v16, g_v16);
    cudaGetSymbolAddress((void**)&vt16, g_vt16);
    cudaGetSymbolAddress((void**)&s16, g_s16);
    cudaGetSymbolAddress((void**)&w16, g_w16);
    cudaGetSymbolAddress((void**)&o32, g_o32);

    cudaFuncSetAttribute(mma_gemm_h<true, true>,   cudaFuncAttributeMaxDynamicSharedMemorySize, SMEM_TOTAL);
    cudaFuncSetAttribute(mma_gemm_h<true, false>,  cudaFuncAttributeMaxDynamicSharedMemorySize, SMEM_TOTAL);
    cudaFuncSetAttribute(mma_gemm_h<false, true>,  cudaFuncAttributeMaxDynamicSharedMemorySize, SMEM_TOTAL);

    const int WN = C_DIM * C_DIM;          // 262144
    __half* wq16 = w16;
    __half* wk16 = w16 + WN;
    __half* wv16 = w16 + 2 * WN;
    __half* wo16 = w16 + 3 * WN;

    // 0. convert weights to fp16
    f2h_kernel<<<WN / 1024, 256>>>(wq, wq16, WN);
    f2h_kernel<<<WN / 1024, 256>>>(wk, wk16, WN);
    f2h_kernel<<<WN / 1024, 256>>>(wv, wv16, WN);
    f2h_kernel<<<WN / 1024, 256>>>(wo, wo16, WN);

    // 1. GroupNorm -> token-major fp16 h
    groupnorm_kernel<<<B_DIM * 32, 256>>>(x, gamma, beta, h16);

    // 2. Q/K/V projections (fp16 out)
    dim3 gproj(C_DIM / BNT, N_TOK / BMT, 1);
    mma_gemm_h<true, true><<<gproj, 256, SMEM_TOTAL>>>(h16, wq16, bq, q16, N_TOK, C_DIM, C_DIM, 0, 0, 0, 1.f);
    mma_gemm_h<true, true><<<gproj, 256, SMEM_TOTAL>>>(h16, wk16, bk, k16, N_TOK, C_DIM, C_DIM, 0, 0, 0, 1.f);
    mma_gemm_h<true, true><<<gproj, 256, SMEM_TOTAL>>>(h16, wv16, bv, v16, N_TOK, C_DIM, C_DIM, 0, 0, 0, 1.f);

    // 3. transpose V to [B][C][HW]
    dim3 tb(32, 8);
    dim3 tg(HW_DIM / 32, C_DIM / 32, B_DIM);
    transpose_h_kernel<<<tg, tb>>>(v16, vt16);

    // 4. scores = ALPHA * Q @ K^T (batched NT, fp16 out)
    dim3 gsc(HW_DIM / BNT, HW_DIM / BMT, B_DIM);
    mma_gemm_h<false, true><<<gsc, 256, SMEM_TOTAL>>>(q16, k16, nullptr, s16, HW_DIM, HW_DIM, C_DIM,
                                                      (long long)HW_DIM * C_DIM,
                                                      (long long)HW_DIM * C_DIM,
                                                      (long long)HW_DIM * HW_DIM, ALPHA_V);

    // 5. softmax over keys (fp16 in-place)
    softmax_h_kernel<<<N_TOK, 256>>>(s16);

    // 6. attn_out = P @ Vt^T (batched NT, fp16 out) -> reuse h16
    dim3 gsv(C_DIM / BNT, HW_DIM / BMT, B_DIM);
    mma_gemm_h<false, true><<<gsv, 256, SMEM_TOTAL>>>(s16, vt16, nullptr, h16, HW_DIM, C_DIM, HW_DIM,
                                                      (long long)HW_DIM * HW_DIM,
                                                      (long long)C_DIM * HW_DIM,
                                                      (long long)HW_DIM * C_DIM, 1.f);

    // 7. output projection (fp32 out)
    mma_gemm_h<true, false><<<gproj, 256, SMEM_TOTAL>>>(h16, wo16, bo, o32, N_TOK, C_DIM, C_DIM, 0, 0, 0, 1.f);

    // 8. transpose back to [B, C, 64, 64] + residual
    add_res_transpose_kernel<<<tg, tb>>>(o32, x, out);
}